// round 12
// baseline (speedup 1.0000x reference)
#include <cuda_runtime.h>
#include <cuda_fp16.h>
#include <cstdint>

#define DINLINE __device__ __forceinline__

static constexpr int BATCH = 65536;
static constexpr int HDIM  = 256;
static constexpr int COMB  = 512;
static constexpr int MT    = 128;     // CTA M tile
static constexpr int NT    = 128;     // CTA N tile (= 32 h-cols x 4 gates)
static constexpr int KCH   = 64;      // K chunk
static constexpr int NCHUNK = COMB / KCH;   // 8
static constexpr int NSTAGE = 3;

static constexpr int SA = 72;                       // smem row stride in halves (144B)
static constexpr uint32_t A_TILE_B = MT * SA * 2;   // 18432
static constexpr uint32_t STAGE_B  = 2 * A_TILE_B;  // 36864 (A then W)
static constexpr uint32_t SMEM_PIPE = NSTAGE * STAGE_B;  // 110592 -> 2 CTAs/SM
static constexpr int GS = 136;                      // gate smem stride (floats)

// ---- fp16 scratch (static device arrays; no allocation) ----
__device__ __half g_A16[(size_t)BATCH * COMB];      // concat(x,h) fp16
__device__ __half g_Wp[(size_t)4 * HDIM * COMB];    // packed: row n = hcol*4+gate

// ============================ PTX helpers ============================
DINLINE uint32_t smem_u32(const void* p) {
    uint32_t a;
    asm("{ .reg .u64 t; cvta.to.shared.u64 t, %1; cvt.u32.u64 %0, t; }" : "=r"(a) : "l"(p));
    return a;
}
DINLINE void cp_async16(uint32_t dst, const void* src) {
    asm volatile("cp.async.cg.shared.global [%0], [%1], 16;" :: "r"(dst), "l"(src));
}
DINLINE void cp_commit() { asm volatile("cp.async.commit_group;" ::: "memory"); }
template <int N> DINLINE void cp_wait() {
    asm volatile("cp.async.wait_group %0;" :: "n"(N) : "memory");
}
DINLINE void ldsm_x4(uint32_t (&r)[4], uint32_t addr) {
    asm volatile("ldmatrix.sync.aligned.m8n8.x4.shared.b16 {%0,%1,%2,%3}, [%4];"
                 : "=r"(r[0]), "=r"(r[1]), "=r"(r[2]), "=r"(r[3]) : "r"(addr));
}
DINLINE void mma16816(float (&d)[4], const uint32_t (&a)[4], const uint32_t* b) {
    asm volatile(
        "mma.sync.aligned.m16n8k16.row.col.f32.f16.f16.f32 "
        "{%0,%1,%2,%3}, {%4,%5,%6,%7}, {%8,%9}, {%0,%1,%2,%3};"
        : "+f"(d[0]), "+f"(d[1]), "+f"(d[2]), "+f"(d[3])
        : "r"(a[0]), "r"(a[1]), "r"(a[2]), "r"(a[3]), "r"(b[0]), "r"(b[1]));
}

// ============================ math helpers ============================
DINLINE float fast_sigmoid(float x) { return __fdividef(1.0f, 1.0f + __expf(-x)); }
DINLINE float fast_tanh(float x) {
    float ax = fabsf(x);
    float e  = __expf(-2.0f * ax);
    float r  = __fdividef(1.0f - e, 1.0f + e);
    return copysignf(r, x);
}

// ============================ merged prepass kernel ============================
// blocks [0, 16384): A16[m][k] = fp16(concat(x,h)[m][k])
// blocks [16384, 16640): Wp row n = hcol*4 + gate <- W_gate[hcol][:]
__global__ void __launch_bounds__(256) convert_aw_kernel(
    const float* __restrict__ x, const float* __restrict__ h,
    const float* __restrict__ Wf, const float* __restrict__ Wi,
    const float* __restrict__ Wo, const float* __restrict__ Wg) {
    if (blockIdx.x < 16384) {
        size_t g  = (size_t)blockIdx.x * 256 + threadIdx.x;
        int m  = (int)(g >> 6);
        int k0 = ((int)g & 63) * 8;
        const float* src = (k0 < 256) ? (x + (size_t)m * 256 + k0)
                                      : (h + (size_t)m * 256 + (k0 - 256));
        float4 a = __ldg((const float4*)src);
        float4 b = __ldg((const float4*)src + 1);
        union { uint4 u; __half2 hh[4]; } pk;
        pk.hh[0] = __floats2half2_rn(a.x, a.y);
        pk.hh[1] = __floats2half2_rn(a.z, a.w);
        pk.hh[2] = __floats2half2_rn(b.x, b.y);
        pk.hh[3] = __floats2half2_rn(b.z, b.w);
        *reinterpret_cast<uint4*>(g_A16 + (size_t)m * COMB + k0) = pk.u;
    } else {
        int g  = (blockIdx.x - 16384) * 256 + threadIdx.x;
        int r  = g >> 6;
        int k0 = (g & 63) * 8;
        int gate = r & 3;
        int hcol = r >> 2;
        const float* W = (gate == 0) ? Wf : (gate == 1) ? Wi : (gate == 2) ? Wo : Wg;
        const float* src = W + (size_t)hcol * COMB + k0;
        float4 a = __ldg((const float4*)src);
        float4 b = __ldg((const float4*)src + 1);
        union { uint4 u; __half2 hh2[4]; } pk;
        pk.hh2[0] = __floats2half2_rn(a.x, a.y);
        pk.hh2[1] = __floats2half2_rn(a.z, a.w);
        pk.hh2[2] = __floats2half2_rn(b.x, b.y);
        pk.hh2[3] = __floats2half2_rn(b.z, b.w);
        *reinterpret_cast<uint4*>(g_Wp + (size_t)r * COMB + k0) = pk.u;
    }
}

// ============================ main fused GEMM+LSTM kernel ============================
// grid (8, 512): blockIdx.x = by (h-col block of 32), blockIdx.y = M tile.
DINLINE void load_stage(uint32_t stb, const __half* gA, const __half* gW,
                        int kc, int t) {
    #pragma unroll
    for (int i = 0; i < 4; i++) {
        int idx = t + i * 256;           // 0..1023
        int m = idx >> 3, c = idx & 7;
        cp_async16(stb + (uint32_t)(m * SA + c * 8) * 2,
                   gA + (size_t)m * COMB + kc + c * 8);
    }
    #pragma unroll
    for (int i = 0; i < 4; i++) {
        int idx = t + i * 256;
        int n = idx >> 3, c = idx & 7;
        cp_async16(stb + A_TILE_B + (uint32_t)(n * SA + c * 8) * 2,
                   gW + (size_t)n * COMB + kc + c * 8);
    }
}

// fragment load for one ks-step (2 A ldsm + 4 B ldsm)
DINLINE void load_frags(uint32_t stb, int ks,
                        int warp_m, int warp_n,
                        int A_row, int A_k, int B_n, int B_k,
                        uint32_t (&af)[2][4], uint32_t (&bf)[8][2]) {
    #pragma unroll
    for (int i = 0; i < 2; i++) {
        uint32_t addr = stb +
            (uint32_t)((warp_m * 32 + i * 16 + A_row) * SA + ks * 16 + A_k) * 2;
        ldsm_x4(af[i], addr);
    }
    #pragma unroll
    for (int jj = 0; jj < 4; jj++) {
        uint32_t r[4];
        uint32_t addr = stb + A_TILE_B +
            (uint32_t)((warp_n * 64 + jj * 16 + B_n) * SA + ks * 16 + B_k) * 2;
        ldsm_x4(r, addr);
        bf[jj * 2][0] = r[0]; bf[jj * 2][1] = r[1];
        bf[jj * 2 + 1][0] = r[2]; bf[jj * 2 + 1][1] = r[3];
    }
}

__global__ void __launch_bounds__(256, 2) lstm_gemm_kernel(
    const float* __restrict__ c_prev,
    const float* __restrict__ b_f, const float* __restrict__ b_i,
    const float* __restrict__ b_o, const float* __restrict__ b_g,
    float* __restrict__ out) {
    extern __shared__ char smem[];
    const uint32_t sbase = smem_u32(smem);
    float* gsm = (float*)smem;

    const int t    = threadIdx.x;
    const int lane = t & 31;
    const int wid  = t >> 5;
    const int warp_m = wid & 3;          // 4 M-warps (32 rows each)
    const int warp_n = wid >> 2;         // 2 N-warps (64 cols each)
    const int by = blockIdx.x;
    const int m0 = blockIdx.y * MT;

    const __half* gA = g_A16 + (size_t)m0 * COMB;
    const __half* gW = g_Wp + (size_t)by * NT * COMB;

    const int A_row = (lane & 7) + ((lane >> 3) & 1) * 8;
    const int A_k   = (lane >> 4) * 8;
    const int B_n   = (lane & 7) + ((lane >> 3) >> 1) * 8;
    const int B_k   = ((lane >> 3) & 1) * 8;

    float acc[2][8][4];
    #pragma unroll
    for (int i = 0; i < 2; i++)
        #pragma unroll
        for (int j = 0; j < 8; j++)
            #pragma unroll
            for (int q = 0; q < 4; q++) acc[i][j][q] = 0.0f;

    #pragma unroll
    for (int s = 0; s < 2; s++) {
        load_stage(sbase + s * STAGE_B, gA, gW, s * KCH, t);
        cp_commit();
    }

    #pragma unroll
    for (int k = 0; k < NCHUNK; k++) {
        if (k < NCHUNK - 1) cp_wait<1>();
        else                cp_wait<0>();
        __syncthreads();

        if (k + 2 < NCHUNK) {
            load_stage(sbase + ((k + 2) % NSTAGE) * STAGE_B, gA, gW,
                       (k + 2) * KCH, t);
            cp_commit();
        }

        const uint32_t stb = sbase + (k % NSTAGE) * STAGE_B;
        // ks-level software pipeline with static double buffers
        uint32_t af[2][2][4];
        uint32_t bf[2][8][2];
        load_frags(stb, 0, warp_m, warp_n, A_row, A_k, B_n, B_k, af[0], bf[0]);
        #pragma unroll
        for (int ks = 0; ks < 4; ks++) {
            const int cur = ks & 1;
            if (ks < 3)
                load_frags(stb, ks + 1, warp_m, warp_n, A_row, A_k, B_n, B_k,
                           af[cur ^ 1], bf[cur ^ 1]);
            #pragma unroll
            for (int i = 0; i < 2; i++)
                #pragma unroll
                for (int j = 0; j < 8; j++)
                    mma16816(acc[i][j], af[cur][i], bf[cur][j]);
        }
    }

    // ---- epilogue thread mapping: 4 consecutive h-cols x 4 rows per thread ----
    const int g8 = t & 7;                // col group (4 hcols = 16 gate cols)
    const int r5 = t >> 3;               // 0..31 row-thread
    const int hcol0 = by * 32 + g8 * 4;
    const size_t RBH = (size_t)BATCH * HDIM;

    // prefetch c_prev (hide DRAM latency under accumulator staging)
    float4 cpre[4];
    #pragma unroll
    for (int it = 0; it < 4; it++) {
        int row = it * 32 + r5;
        cpre[it] = __ldg((const float4*)(c_prev + (size_t)(m0 + row) * HDIM + hcol0));
    }
    const float4 bF = __ldg((const float4*)(b_f + hcol0));
    const float4 bI = __ldg((const float4*)(b_i + hcol0));
    const float4 bO = __ldg((const float4*)(b_o + hcol0));
    const float4 bG = __ldg((const float4*)(b_g + hcol0));

    // ---- stage raw gate values to smem ----
    __syncthreads();
    {
        const int g = lane >> 2, tig = lane & 3;
        #pragma unroll
        for (int i = 0; i < 2; i++) {
            #pragma unroll
            for (int j = 0; j < 8; j++) {
                int r0 = warp_m * 32 + i * 16 + g;
                int n0 = warp_n * 64 + j * 8 + tig * 2;
                *(float2*)(gsm + r0 * GS + n0)       = make_float2(acc[i][j][0], acc[i][j][1]);
                *(float2*)(gsm + (r0 + 8) * GS + n0) = make_float2(acc[i][j][2], acc[i][j][3]);
            }
        }
    }
    __syncthreads();

    // ---- activation epilogue: float4 stores ----
    #pragma unroll
    for (int it = 0; it < 4; it++) {
        int row = it * 32 + r5;
        const float* src = gsm + row * GS + g8 * 16;
        float4 q0 = *(const float4*)(src + 0);   // (f,i,o,g) hcol0+0
        float4 q1 = *(const float4*)(src + 4);   // hcol0+1
        float4 q2 = *(const float4*)(src + 8);   // hcol0+2
        float4 q3 = *(const float4*)(src + 12);  // hcol0+3
        float4 cp = cpre[it];

        float4 F, I, O, G, C, H;
        {
            float f = fast_sigmoid(q0.x + bF.x);
            float i = fast_sigmoid(q0.y + bI.x);
            float o = fast_sigmoid(q0.z + bO.x);
            float g = fast_tanh(q0.w + bG.x);
            float c = f * cp.x + i * g;
            F.x = f; I.x = i; O.x = o; G.x = g; C.x = c; H.x = o * fast_tanh(c);
        }
        {
            float f = fast_sigmoid(q1.x + bF.y);
            float i = fast_sigmoid(q1.y + bI.y);
            float o = fast_sigmoid(q1.z + bO.y);
            float g = fast_tanh(q1.w + bG.y);
            float c = f * cp.y + i * g;
            F.y = f; I.y = i; O.y = o; G.y = g; C.y = c; H.y = o * fast_tanh(c);
        }
        {
            float f = fast_sigmoid(q2.x + bF.z);
            float i = fast_sigmoid(q2.y + bI.z);
            float o = fast_sigmoid(q2.z + bO.z);
            float g = fast_tanh(q2.w + bG.z);
            float c = f * cp.z + i * g;
            F.z = f; I.z = i; O.z = o; G.z = g; C.z = c; H.z = o * fast_tanh(c);
        }
        {
            float f = fast_sigmoid(q3.x + bF.w);
            float i = fast_sigmoid(q3.y + bI.w);
            float o = fast_sigmoid(q3.z + bO.w);
            float g = fast_tanh(q3.w + bG.w);
            float c = f * cp.w + i * g;
            F.w = f; I.w = i; O.w = o; G.w = g; C.w = c; H.w = o * fast_tanh(c);
        }

        size_t idx = (size_t)(m0 + row) * HDIM + hcol0;
        *(float4*)(out + idx)           = H;
        *(float4*)(out + RBH + idx)     = C;
        *(float4*)(out + 2 * RBH + idx) = F;
        *(float4*)(out + 3 * RBH + idx) = I;
        *(float4*)(out + 4 * RBH + idx) = O;
        *(float4*)(out + 5 * RBH + idx) = G;
    }
}

// ============================ host launch ============================
extern "C" void kernel_launch(void* const* d_in, const int* in_sizes, int n_in,
                              void* d_out, int out_size) {
    const float* x_t    = (const float*)d_in[0];
    const float* h_prev = (const float*)d_in[1];
    const float* c_prev = (const float*)d_in[2];
    const float* W_f    = (const float*)d_in[3];
    const float* b_f    = (const float*)d_in[4];
    const float* W_i    = (const float*)d_in[5];
    const float* b_i    = (const float*)d_in[6];
    const float* W_o    = (const float*)d_in[7];
    const float* b_o    = (const float*)d_in[8];
    const float* W_g    = (const float*)d_in[9];
    const float* b_g    = (const float*)d_in[10];
    float* out = (float*)d_out;

    static bool attr_set = false;
    if (!attr_set) {
        cudaFuncSetAttribute(lstm_gemm_kernel,
                             cudaFuncAttributeMaxDynamicSharedMemorySize, SMEM_PIPE);
        attr_set = true;
    }

    convert_aw_kernel<<<16640, 256>>>(x_t, h_prev, W_f, W_i, W_o, W_g);
    lstm_gemm_kernel<<<dim3(8, BATCH / MT), 256, SMEM_PIPE>>>(
        c_prev, b_f, b_i, b_o, b_g, out);
}

// round 13
// speedup vs baseline: 1.1007x; 1.1007x over previous
#include <cuda_runtime.h>
#include <cuda_fp16.h>
#include <cstdint>

#define DINLINE __device__ __forceinline__

static constexpr int BATCH = 65536;
static constexpr int HDIM  = 256;
static constexpr int COMB  = 512;
static constexpr int MT    = 128;     // CTA M tile
static constexpr int NT    = 128;     // CTA N tile (= 32 h-cols x 4 gates)
static constexpr int KCH   = 64;      // K chunk
static constexpr int NCHUNK = COMB / KCH;   // 8
static constexpr int NSTAGE = 3;

static constexpr int SA = 72;                       // smem row stride in halves (144B)
static constexpr uint32_t A_TILE_B = MT * SA * 2;   // 18432
static constexpr uint32_t STAGE_B  = 2 * A_TILE_B;  // 36864 (A then W)
static constexpr uint32_t SMEM_PIPE = NSTAGE * STAGE_B;  // 110592 -> 2 CTAs/SM
static constexpr int GS = 136;                      // gate smem stride (floats)

// ---- fp16 scratch (static device arrays; no allocation) ----
__device__ __half g_A16[(size_t)BATCH * COMB];      // concat(x,h) fp16
__device__ __half g_Wp[(size_t)4 * HDIM * COMB];    // packed: row n = hcol*4+gate

// ============================ PTX helpers ============================
DINLINE uint32_t smem_u32(const void* p) {
    uint32_t a;
    asm("{ .reg .u64 t; cvta.to.shared.u64 t, %1; cvt.u32.u64 %0, t; }" : "=r"(a) : "l"(p));
    return a;
}
DINLINE void cp_async16(uint32_t dst, const void* src) {
    asm volatile("cp.async.cg.shared.global [%0], [%1], 16;" :: "r"(dst), "l"(src));
}
DINLINE void cp_commit() { asm volatile("cp.async.commit_group;" ::: "memory"); }
template <int N> DINLINE void cp_wait() {
    asm volatile("cp.async.wait_group %0;" :: "n"(N) : "memory");
}
DINLINE void ldsm_x4(uint32_t (&r)[4], uint32_t addr) {
    asm volatile("ldmatrix.sync.aligned.m8n8.x4.shared.b16 {%0,%1,%2,%3}, [%4];"
                 : "=r"(r[0]), "=r"(r[1]), "=r"(r[2]), "=r"(r[3]) : "r"(addr));
}
DINLINE void mma16816(float (&d)[4], const uint32_t (&a)[4], const uint32_t* b) {
    asm volatile(
        "mma.sync.aligned.m16n8k16.row.col.f32.f16.f16.f32 "
        "{%0,%1,%2,%3}, {%4,%5,%6,%7}, {%8,%9}, {%0,%1,%2,%3};"
        : "+f"(d[0]), "+f"(d[1]), "+f"(d[2]), "+f"(d[3])
        : "r"(a[0]), "r"(a[1]), "r"(a[2]), "r"(a[3]), "r"(b[0]), "r"(b[1]));
}

// ============================ math helpers ============================
DINLINE float fast_sigmoid(float x) { return __fdividef(1.0f, 1.0f + __expf(-x)); }
DINLINE float fast_tanh(float x) {
    float ax = fabsf(x);
    float e  = __expf(-2.0f * ax);
    float r  = __fdividef(1.0f - e, 1.0f + e);
    return copysignf(r, x);
}

// ============================ merged prepass kernel ============================
// blocks [0, 16384): A16[m][k] = fp16(concat(x,h)[m][k])
// blocks [16384, 16640): Wp row n = hcol*4 + gate <- W_gate[hcol][:]
__global__ void __launch_bounds__(256) convert_aw_kernel(
    const float* __restrict__ x, const float* __restrict__ h,
    const float* __restrict__ Wf, const float* __restrict__ Wi,
    const float* __restrict__ Wo, const float* __restrict__ Wg) {
    if (blockIdx.x < 16384) {
        size_t g  = (size_t)blockIdx.x * 256 + threadIdx.x;
        int m  = (int)(g >> 6);
        int k0 = ((int)g & 63) * 8;
        const float* src = (k0 < 256) ? (x + (size_t)m * 256 + k0)
                                      : (h + (size_t)m * 256 + (k0 - 256));
        float4 a = __ldg((const float4*)src);
        float4 b = __ldg((const float4*)src + 1);
        union { uint4 u; __half2 hh[4]; } pk;
        pk.hh[0] = __floats2half2_rn(a.x, a.y);
        pk.hh[1] = __floats2half2_rn(a.z, a.w);
        pk.hh[2] = __floats2half2_rn(b.x, b.y);
        pk.hh[3] = __floats2half2_rn(b.z, b.w);
        *reinterpret_cast<uint4*>(g_A16 + (size_t)m * COMB + k0) = pk.u;
    } else {
        int g  = (blockIdx.x - 16384) * 256 + threadIdx.x;
        int r  = g >> 6;
        int k0 = (g & 63) * 8;
        int gate = r & 3;
        int hcol = r >> 2;
        const float* W = (gate == 0) ? Wf : (gate == 1) ? Wi : (gate == 2) ? Wo : Wg;
        const float* src = W + (size_t)hcol * COMB + k0;
        float4 a = __ldg((const float4*)src);
        float4 b = __ldg((const float4*)src + 1);
        union { uint4 u; __half2 hh2[4]; } pk;
        pk.hh2[0] = __floats2half2_rn(a.x, a.y);
        pk.hh2[1] = __floats2half2_rn(a.z, a.w);
        pk.hh2[2] = __floats2half2_rn(b.x, b.y);
        pk.hh2[3] = __floats2half2_rn(b.z, b.w);
        *reinterpret_cast<uint4*>(g_Wp + (size_t)r * COMB + k0) = pk.u;
    }
}

// ============================ main fused GEMM+LSTM kernel ============================
// grid (8, 512): blockIdx.x = by (h-col block of 32), blockIdx.y = M tile.
DINLINE void load_stage(uint32_t stb, const __half* gA, const __half* gW,
                        int kc, int t) {
    #pragma unroll
    for (int i = 0; i < 4; i++) {
        int idx = t + i * 256;           // 0..1023
        int m = idx >> 3, c = idx & 7;
        cp_async16(stb + (uint32_t)(m * SA + c * 8) * 2,
                   gA + (size_t)m * COMB + kc + c * 8);
    }
    #pragma unroll
    for (int i = 0; i < 4; i++) {
        int idx = t + i * 256;
        int n = idx >> 3, c = idx & 7;
        cp_async16(stb + A_TILE_B + (uint32_t)(n * SA + c * 8) * 2,
                   gW + (size_t)n * COMB + kc + c * 8);
    }
}

// fragment load for one ks-step (2 A ldsm + 4 B ldsm)
DINLINE void load_frags(uint32_t stb, int ks,
                        int warp_m, int warp_n,
                        int A_row, int A_k, int B_n, int B_k,
                        uint32_t (&af)[2][4], uint32_t (&bf)[8][2]) {
    #pragma unroll
    for (int i = 0; i < 2; i++) {
        uint32_t addr = stb +
            (uint32_t)((warp_m * 32 + i * 16 + A_row) * SA + ks * 16 + A_k) * 2;
        ldsm_x4(af[i], addr);
    }
    #pragma unroll
    for (int jj = 0; jj < 4; jj++) {
        uint32_t r[4];
        uint32_t addr = stb + A_TILE_B +
            (uint32_t)((warp_n * 64 + jj * 16 + B_n) * SA + ks * 16 + B_k) * 2;
        ldsm_x4(r, addr);
        bf[jj * 2][0] = r[0]; bf[jj * 2][1] = r[1];
        bf[jj * 2 + 1][0] = r[2]; bf[jj * 2 + 1][1] = r[3];
    }
}

__global__ void __launch_bounds__(256, 2) lstm_gemm_kernel(
    const float* __restrict__ c_prev,
    const float* __restrict__ b_f, const float* __restrict__ b_i,
    const float* __restrict__ b_o, const float* __restrict__ b_g,
    float* __restrict__ out) {
    extern __shared__ char smem[];
    const uint32_t sbase = smem_u32(smem);
    float* gsm = (float*)smem;

    const int t    = threadIdx.x;
    const int lane = t & 31;
    const int wid  = t >> 5;
    const int warp_m = wid & 3;          // 4 M-warps (32 rows each)
    const int warp_n = wid >> 2;         // 2 N-warps (64 cols each)
    const int by = blockIdx.x;
    const int m0 = blockIdx.y * MT;

    const __half* gA = g_A16 + (size_t)m0 * COMB;
    const __half* gW = g_Wp + (size_t)by * NT * COMB;

    const int A_row = (lane & 7) + ((lane >> 3) & 1) * 8;
    const int A_k   = (lane >> 4) * 8;
    const int B_n   = (lane & 7) + ((lane >> 3) >> 1) * 8;
    const int B_k   = ((lane >> 3) & 1) * 8;

    float acc[2][8][4];
    #pragma unroll
    for (int i = 0; i < 2; i++)
        #pragma unroll
        for (int j = 0; j < 8; j++)
            #pragma unroll
            for (int q = 0; q < 4; q++) acc[i][j][q] = 0.0f;

    #pragma unroll
    for (int s = 0; s < 2; s++) {
        load_stage(sbase + s * STAGE_B, gA, gW, s * KCH, t);
        cp_commit();
    }

    #pragma unroll
    for (int k = 0; k < NCHUNK; k++) {
        if (k < NCHUNK - 1) cp_wait<1>();
        else                cp_wait<0>();
        __syncthreads();

        if (k + 2 < NCHUNK) {
            load_stage(sbase + ((k + 2) % NSTAGE) * STAGE_B, gA, gW,
                       (k + 2) * KCH, t);
            cp_commit();
        }

        const uint32_t stb = sbase + (k % NSTAGE) * STAGE_B;
        // ks-level software pipeline with static double buffers
        uint32_t af[2][2][4];
        uint32_t bf[2][8][2];
        load_frags(stb, 0, warp_m, warp_n, A_row, A_k, B_n, B_k, af[0], bf[0]);
        #pragma unroll
        for (int ks = 0; ks < 4; ks++) {
            const int cur = ks & 1;
            if (ks < 3)
                load_frags(stb, ks + 1, warp_m, warp_n, A_row, A_k, B_n, B_k,
                           af[cur ^ 1], bf[cur ^ 1]);
            #pragma unroll
            for (int i = 0; i < 2; i++)
                #pragma unroll
                for (int j = 0; j < 8; j++)
                    mma16816(acc[i][j], af[cur][i], bf[cur][j]);
        }
    }

    // ---- prefetch c_prev for the epilogue (hide DRAM latency under staging) ----
    const int hc   = t & 31;
    const int rblk = t >> 5;
    const int hcol = by * 32 + hc;
    const size_t RBH = (size_t)BATCH * HDIM;
    float cpre[16];
    #pragma unroll
    for (int it = 0; it < 16; it++) {
        int row = it * 8 + rblk;
        cpre[it] = __ldg(c_prev + (size_t)(m0 + row) * HDIM + hcol);
    }

    // ---- stage raw gate values to smem ----
    __syncthreads();
    {
        const int g = lane >> 2, tig = lane & 3;
        #pragma unroll
        for (int i = 0; i < 2; i++) {
            #pragma unroll
            for (int j = 0; j < 8; j++) {
                int r0 = warp_m * 32 + i * 16 + g;
                int n0 = warp_n * 64 + j * 8 + tig * 2;
                *(float2*)(gsm + r0 * GS + n0)       = make_float2(acc[i][j][0], acc[i][j][1]);
                *(float2*)(gsm + (r0 + 8) * GS + n0) = make_float2(acc[i][j][2], acc[i][j][3]);
            }
        }
    }
    __syncthreads();

    // ---- activation epilogue: fully coalesced ----
    const float bF = __ldg(b_f + hcol), bI = __ldg(b_i + hcol);
    const float bO = __ldg(b_o + hcol), bG = __ldg(b_g + hcol);

    #pragma unroll
    for (int it = 0; it < 16; it++) {
        int row = it * 8 + rblk;
        float4 gv = *(float4*)(gsm + row * GS + hc * 4);  // (f,i,o,g)
        size_t idx = (size_t)(m0 + row) * HDIM + hcol;
        float f = fast_sigmoid(gv.x + bF);
        float i = fast_sigmoid(gv.y + bI);
        float o = fast_sigmoid(gv.z + bO);
        float g = fast_tanh(gv.w + bG);
        float c = f * cpre[it] + i * g;
        float h = o * fast_tanh(c);
        out[idx]           = h;
        out[RBH + idx]     = c;
        out[2 * RBH + idx] = f;
        out[3 * RBH + idx] = i;
        out[4 * RBH + idx] = o;
        out[5 * RBH + idx] = g;
    }
}

// ============================ host launch ============================
extern "C" void kernel_launch(void* const* d_in, const int* in_sizes, int n_in,
                              void* d_out, int out_size) {
    const float* x_t    = (const float*)d_in[0];
    const float* h_prev = (const float*)d_in[1];
    const float* c_prev = (const float*)d_in[2];
    const float* W_f    = (const float*)d_in[3];
    const float* b_f    = (const float*)d_in[4];
    const float* W_i    = (const float*)d_in[5];
    const float* b_i    = (const float*)d_in[6];
    const float* W_o    = (const float*)d_in[7];
    const float* b_o    = (const float*)d_in[8];
    const float* W_g    = (const float*)d_in[9];
    const float* b_g    = (const float*)d_in[10];
    float* out = (float*)d_out;

    static bool attr_set = false;
    if (!attr_set) {
        cudaFuncSetAttribute(lstm_gemm_kernel,
                             cudaFuncAttributeMaxDynamicSharedMemorySize, SMEM_PIPE);
        attr_set = true;
    }

    convert_aw_kernel<<<16640, 256>>>(x_t, h_prev, W_f, W_i, W_o, W_g);
    lstm_gemm_kernel<<<dim3(8, BATCH / MT), 256, SMEM_PIPE>>>(
        c_prev, b_f, b_i, b_o, b_g, out);
}